// round 7
// baseline (speedup 1.0000x reference)
#include <cuda_runtime.h>
#include <cstdint>

#define NPAIR 1024
#define THREADS 256

// ---- float-index smem offsets (compact: ~71 KB) ----
#define SA    0        // A fragments: [mt(8)][kt(16)][lane(32)][4]
#define B1S   16384
#define GS    16512
#define BTS   16640
#define SAW   16768    // [2][128]
#define PART  17024    // [mg(4)][col(128)]
#define SUMS  17536    // float2 [ng(2)][row(128)]
#define MASKI 18048    // 128 ints
#define PVI   18176    // 2 ints
#define SMEM_BYTES (18184 * 4)

__device__ __align__(256) float gBW1[3 * 16384];
__device__ __align__(256) float gBW2[3 * 16384];

__device__ __forceinline__ uint32_t to_tf32(float x) {
    uint32_t r; asm("cvt.rna.tf32.f32 %0, %1;" : "=r"(r) : "f"(x)); return r;
}
__device__ __forceinline__ float to_tf32f(float x) { return __uint_as_float(to_tf32(x)); }

__device__ __forceinline__ void mma8(float* c, uint32_t a0, uint32_t a1, uint32_t a2, uint32_t a3,
                                     uint32_t b0, uint32_t b1) {
    asm("mma.sync.aligned.m16n8k8.row.col.f32.tf32.tf32.f32 "
        "{%0,%1,%2,%3}, {%4,%5,%6,%7}, {%8,%9}, {%0,%1,%2,%3};"
        : "+f"(c[0]), "+f"(c[1]), "+f"(c[2]), "+f"(c[3])
        : "r"(a0), "r"(a1), "r"(a2), "r"(a3), "r"(b0), "r"(b1));
}

// ---------- prep: fragment-layout tf32 weight images ----------
__global__ void prep_kernel(const float* __restrict__ W1, const float* __restrict__ W2) {
    int b = blockIdx.x;            // 0..5
    int layer = b >> 1, isW2 = b & 1;
    const float* src = isW2 ? (W2 + layer * 256 * 128) : (W1 + layer * 128 * 128);
    float* dst = isW2 ? (gBW2 + layer * 16384) : (gBW1 + layer * 16384);
    for (int idx = threadIdx.x; idx < 16384; idx += blockDim.x) {
        int j = idx & 1, lane = (idx >> 1) & 31, kt = (idx >> 6) & 15, nt = idx >> 10;
        int g = lane >> 2, t = lane & 3;
        dst[idx] = to_tf32f(src[(kt * 8 + t + j * 4) * 128 + nt * 8 + g]);
    }
}

extern __shared__ float smem[];

// warp (mg,ng): rows mg*32..+31, cols ng*64..+63. B fragments streamed from L2 via LDG.
__device__ __forceinline__ void gemm64(const float* sm, const float* gB, int lid, int mg, int ng,
                                       float acc[2][8][4]) {
    #pragma unroll
    for (int m = 0; m < 2; m++)
        #pragma unroll
        for (int nt = 0; nt < 8; nt++)
            #pragma unroll
            for (int j = 0; j < 4; j++) acc[m][nt][j] = 0.0f;
    const int mt0 = mg * 2, mt1 = mt0 + 1;
    const float* base = gB + ng * 8192 + lid * 2;
    uint2 Bk[8];
    #pragma unroll
    for (int ntl = 0; ntl < 8; ntl++) Bk[ntl] = __ldg((const uint2*)(base + ntl * 1024));
    #pragma unroll 1
    for (int kt = 0; kt < 16; kt++) {
        const int ktn = (kt + 1 < 16) ? kt + 1 : 15;
        uint2 Bn[8];
        #pragma unroll
        for (int ntl = 0; ntl < 8; ntl++)
            Bn[ntl] = __ldg((const uint2*)(base + ntl * 1024 + ktn * 64));
        uint4 A0 = *(const uint4*)(sm + SA + ((mt0 * 16 + kt) * 32 + lid) * 4);
        uint4 A1 = *(const uint4*)(sm + SA + ((mt1 * 16 + kt) * 32 + lid) * 4);
        #pragma unroll
        for (int ntl = 0; ntl < 8; ntl++) {
            mma8(acc[0][ntl], A0.x, A0.z, A0.y, A0.w, Bk[ntl].x, Bk[ntl].y);
            mma8(acc[1][ntl], A1.x, A1.z, A1.y, A1.w, Bk[ntl].x, Bk[ntl].y);
        }
        #pragma unroll
        for (int ntl = 0; ntl < 8; ntl++) Bk[ntl] = Bn[ntl];
    }
}

__global__ __launch_bounds__(THREADS, 2)
void poly_mma_kernel(const float* __restrict__ x, const int* __restrict__ mask,
                     const float* __restrict__ b1,
                     const float* __restrict__ lng, const float* __restrict__ lnb,
                     const float* __restrict__ W2, const float* __restrict__ b2,
                     float* __restrict__ out)
{
    const int tid = threadIdx.x;
    const int lid = tid & 31;
    const int warp = tid >> 5;
    const int mg = warp >> 1, ng = warp & 1;
    const int gq = lid >> 2, tq = lid & 3;
    const int bid = blockIdx.x;
    // conflict-free SA writer role: this thread writes lane_t = Lw, o = o_w
    const int o_w = tq >> 1;
    const int Lw  = (tq >> 1) | ((tq & 1) << 1);
    const bool ownFirst = (tq < 2);
    int* sMask = (int*)(smem + MASKI);
    int* sPv   = (int*)(smem + PVI);

    if (tid < 128) sMask[tid] = mask[bid * 128 + tid];
    __syncthreads();
    if (tid < 2) {
        int pv = 0;
        #pragma unroll 8
        for (int p = 0; p < 64; p++) pv |= sMask[tid * 64 + p];
        sPv[tid] = pv;
    }
    __syncthreads();

    // ---- load x: thread = (row, col-half) -> A fragments (tf32) ----
    {
        const int row = tid >> 1, half = tid & 1;
        float hx[64];
        const float4* xr = (const float4*)(x + ((size_t)bid * 128 + row) * 128 + half * 64);
        const int pvMine = sPv[row >> 6];
        #pragma unroll
        for (int k = 0; k < 16; k++) {
            float4 v = xr[k];
            if (!pvMine) { v.x = 0; v.y = 0; v.z = 0; v.w = 0; }
            hx[4*k] = v.x; hx[4*k+1] = v.y; hx[4*k+2] = v.z; hx[4*k+3] = v.w;
        }
        const int mt = row >> 4, g = row & 15, gl = g & 7, jb = (g >> 3) * 2;
        #pragma unroll
        for (int ktl = 0; ktl < 8; ktl++) {
            int kt = half * 8 + ktl;
            #pragma unroll
            for (int t = 0; t < 4; t++) {
                int base = SA + ((mt * 16 + kt) * 32 + gl * 4 + t) * 4 + jb;
                smem[base]     = to_tf32f(hx[ktl * 8 + t]);
                smem[base + 1] = to_tf32f(hx[ktl * 8 + t + 4]);
            }
        }
    }

    float acc[2][8][4];

    for (int layer = 0; layer < 3; layer++) {
        if (tid < 128) {
            smem[B1S + tid] = b1[layer * 128 + tid];
            smem[GS  + tid] = lng[layer * 128 + tid];
            smem[BTS + tid] = lnb[layer * 128 + tid];
        }
        __syncthreads();                                  // S1: SA + vectors ready

        // ===== GEMM1: h @ W1 (B from L2) =====
        gemm64(smem, gBW1 + layer * 16384, lid, mg, ng, acc);

        // ===== epilogue 1: +b1, LN, ReLU; SA write (STS.128); partial col-max =====
        {
            const int pvMine = sPv[mg >> 1];
            bool vld[2][2];
            #pragma unroll
            for (int mt = 0; mt < 2; mt++)
                #pragma unroll
                for (int sb = 0; sb < 2; sb++) {
                    int r = mg * 32 + mt * 16 + gq + sb * 8;
                    vld[mt][sb] = pvMine ? (sMask[r] != 0) : true;
                }
            float s[2][2] = {{0,0},{0,0}}, q[2][2] = {{0,0},{0,0}};
            #pragma unroll
            for (int mt = 0; mt < 2; mt++)
                #pragma unroll
                for (int ntl = 0; ntl < 8; ntl++) {
                    int c0 = ng * 64 + ntl * 8 + 2 * tq;
                    float b0v = smem[B1S + c0], b1v = smem[B1S + c0 + 1];
                    float* a = acc[mt][ntl];
                    a[0] += b0v; a[1] += b1v; a[2] += b0v; a[3] += b1v;
                    s[mt][0] += a[0] + a[1]; q[mt][0] += a[0]*a[0] + a[1]*a[1];
                    s[mt][1] += a[2] + a[3]; q[mt][1] += a[2]*a[2] + a[3]*a[3];
                }
            #pragma unroll
            for (int mt = 0; mt < 2; mt++)
                #pragma unroll
                for (int sb = 0; sb < 2; sb++) {
                    s[mt][sb] += __shfl_xor_sync(0xffffffffu, s[mt][sb], 1);
                    s[mt][sb] += __shfl_xor_sync(0xffffffffu, s[mt][sb], 2);
                    q[mt][sb] += __shfl_xor_sync(0xffffffffu, q[mt][sb], 1);
                    q[mt][sb] += __shfl_xor_sync(0xffffffffu, q[mt][sb], 2);
                }
            if (tq == 0) {
                float2* su = (float2*)(smem + SUMS);
                #pragma unroll
                for (int mt = 0; mt < 2; mt++)
                    #pragma unroll
                    for (int sb = 0; sb < 2; sb++) {
                        int r = mg * 32 + mt * 16 + gq + sb * 8;
                        su[ng * 128 + r] = make_float2(s[mt][sb], q[mt][sb]);
                    }
            }
            __syncthreads();                               // S2: sums ready; GEMM1 reads done
            float mean[2][2], rstd[2][2];
            {
                const float2* su = (const float2*)(smem + SUMS);
                #pragma unroll
                for (int mt = 0; mt < 2; mt++)
                    #pragma unroll
                    for (int sb = 0; sb < 2; sb++) {
                        int r = mg * 32 + mt * 16 + gq + sb * 8;
                        float2 u = su[r], v = su[128 + r];
                        float m = (u.x + v.x) * (1.0f / 128.0f);
                        float var = (u.y + v.y) * (1.0f / 128.0f) - m * m;
                        mean[mt][sb] = m;
                        rstd[mt][sb] = rsqrtf(var + 1e-5f);
                    }
            }
            float pm[8][2];
            #pragma unroll
            for (int ntl = 0; ntl < 8; ntl++) { pm[ntl][0] = -INFINITY; pm[ntl][1] = -INFINITY; }
            #pragma unroll
            for (int mt = 0; mt < 2; mt++)
                #pragma unroll
                for (int ntl = 0; ntl < 8; ntl++) {
                    int nt = ng * 8 + ntl;
                    int c0 = nt * 8 + 2 * tq;
                    float g0 = smem[GS + c0], g1 = smem[GS + c0 + 1];
                    float t0 = smem[BTS + c0], t1 = smem[BTS + c0 + 1];
                    float v2[2][2];  // [sb][o]
                    #pragma unroll
                    for (int idx = 0; idx < 4; idx++) {
                        int sb = idx >> 1, o = idx & 1;
                        float hv = fmaxf(fmaf((acc[mt][ntl][idx] - mean[mt][sb]) * rstd[mt][sb],
                                              o ? g1 : g0, o ? t1 : t0), 0.0f);
                        v2[sb][o] = to_tf32f(hv);
                        pm[ntl][o] = fmaxf(pm[ntl][o], vld[mt][sb] ? hv : -INFINITY);
                    }
                    // quad exchange -> one STS.128
                    float own0 = v2[0][o_w], own1 = v2[1][o_w];
                    float rcv0 = __shfl_xor_sync(0xffffffffu, v2[0][1 - o_w], 2);
                    float rcv1 = __shfl_xor_sync(0xffffffffu, v2[1][1 - o_w], 2);
                    float4 w = ownFirst ? make_float4(own0, rcv0, own1, rcv1)
                                        : make_float4(rcv0, own0, rcv1, own1);
                    *(float4*)(smem + SA + (((mg * 2 + mt) * 16 + nt) * 32 + gq * 4 + Lw) * 4) = w;
                }
            #pragma unroll
            for (int ntl = 0; ntl < 8; ntl++) {
                #pragma unroll
                for (int off = 4; off <= 16; off <<= 1) {
                    pm[ntl][0] = fmaxf(pm[ntl][0], __shfl_xor_sync(0xffffffffu, pm[ntl][0], off));
                    pm[ntl][1] = fmaxf(pm[ntl][1], __shfl_xor_sync(0xffffffffu, pm[ntl][1], off));
                }
                if (gq == 0) {
                    smem[PART + mg * 128 + ng * 64 + ntl * 8 + 2 * tq]     = pm[ntl][0];
                    smem[PART + mg * 128 + ng * 64 + ntl * 8 + 2 * tq + 1] = pm[ntl][1];
                }
            }
        }
        __syncthreads();                                    // S3: PART + SA(h2) ready

        // ---- aggW = b2 + (max over points) @ W2b, 256 threads ----
        {
            int poly = tid >> 7, col = tid & 127;
            float sacc = b2[layer * 128 + col];
            const float* w2b = W2 + layer * 256 * 128 + 128 * 128 + col;
            const float* p0 = smem + PART + poly * 256;
            #pragma unroll 8
            for (int d = 0; d < 128; d++) {
                float a = fmaxf(p0[d], p0[128 + d]);
                sacc = fmaf(a, __ldg(w2b + d * 128), sacc);
            }
            smem[SAW + poly * 128 + col] = sacc;
        }
        __syncthreads();                                    // S4: SAW ready

        // ===== GEMM2: h2 @ W2a (B from L2) =====
        gemm64(smem, gBW2 + layer * 16384, lid, mg, ng, acc);
        __syncthreads();                                    // S4b: all GEMM2 SA reads done

        // ===== epilogue 2: + aggW ; SA write (STS.128) or final partial max =====
        {
            const float* saw = smem + SAW + (mg >> 1) * 128;
            if (layer < 2) {
                #pragma unroll
                for (int mt = 0; mt < 2; mt++)
                    #pragma unroll
                    for (int ntl = 0; ntl < 8; ntl++) {
                        int nt = ng * 8 + ntl;
                        int c0 = nt * 8 + 2 * tq;
                        float w0 = saw[c0], w1 = saw[c0 + 1];
                        float v2[2][2];
                        #pragma unroll
                        for (int idx = 0; idx < 4; idx++) {
                            int sb = idx >> 1, o = idx & 1;
                            v2[sb][o] = to_tf32f(acc[mt][ntl][idx] + (o ? w1 : w0));
                        }
                        float own0 = v2[0][o_w], own1 = v2[1][o_w];
                        float rcv0 = __shfl_xor_sync(0xffffffffu, v2[0][1 - o_w], 2);
                        float rcv1 = __shfl_xor_sync(0xffffffffu, v2[1][1 - o_w], 2);
                        float4 w = ownFirst ? make_float4(own0, rcv0, own1, rcv1)
                                            : make_float4(rcv0, own0, rcv1, own1);
                        *(float4*)(smem + SA + (((mg * 2 + mt) * 16 + nt) * 32 + gq * 4 + Lw) * 4) = w;
                    }
            } else {
                const int pvMine = sPv[mg >> 1];
                bool vld[2][2];
                #pragma unroll
                for (int mt = 0; mt < 2; mt++)
                    #pragma unroll
                    for (int sb = 0; sb < 2; sb++) {
                        int r = mg * 32 + mt * 16 + gq + sb * 8;
                        vld[mt][sb] = pvMine ? (sMask[r] != 0) : true;
                    }
                float pm[8][2];
                #pragma unroll
                for (int ntl = 0; ntl < 8; ntl++) { pm[ntl][0] = -INFINITY; pm[ntl][1] = -INFINITY; }
                #pragma unroll
                for (int mt = 0; mt < 2; mt++)
                    #pragma unroll
                    for (int ntl = 0; ntl < 8; ntl++) {
                        int c0 = ng * 64 + ntl * 8 + 2 * tq;
                        float w0 = saw[c0], w1 = saw[c0 + 1];
                        #pragma unroll
                        for (int idx = 0; idx < 4; idx++) {
                            int sb = idx >> 1, o = idx & 1;
                            float v = acc[mt][ntl][idx] + (o ? w1 : w0);
                            pm[ntl][o] = fmaxf(pm[ntl][o], vld[mt][sb] ? v : -INFINITY);
                        }
                    }
                #pragma unroll
                for (int ntl = 0; ntl < 8; ntl++) {
                    #pragma unroll
                    for (int off = 4; off <= 16; off <<= 1) {
                        pm[ntl][0] = fmaxf(pm[ntl][0], __shfl_xor_sync(0xffffffffu, pm[ntl][0], off));
                        pm[ntl][1] = fmaxf(pm[ntl][1], __shfl_xor_sync(0xffffffffu, pm[ntl][1], off));
                    }
                    if (gq == 0) {
                        smem[PART + mg * 128 + ng * 64 + ntl * 8 + 2 * tq]     = pm[ntl][0];
                        smem[PART + mg * 128 + ng * 64 + ntl * 8 + 2 * tq + 1] = pm[ntl][1];
                    }
                }
            }
        }
        __syncthreads();                                    // S5: SA/PART ready for next phase
    }

    {
        int poly = tid >> 7, col = tid & 127;
        float m = fmaxf(smem[PART + poly * 256 + col], smem[PART + poly * 256 + 128 + col]);
        out[(size_t)(bid * 2 + poly) * 128 + col] = sPv[poly] ? m : 0.0f;
    }
}

extern "C" void kernel_launch(void* const* d_in, const int* in_sizes, int n_in,
                              void* d_out, int out_size) {
    const float* x    = (const float*)d_in[0];
    const int*   mask = (const int*)d_in[1];
    const float* W1   = (const float*)d_in[2];
    const float* b1   = (const float*)d_in[3];
    const float* lng  = (const float*)d_in[4];
    const float* lnb  = (const float*)d_in[5];
    const float* W2   = (const float*)d_in[6];
    const float* b2   = (const float*)d_in[7];
    float*       out  = (float*)d_out;

    prep_kernel<<<6, 256>>>(W1, W2);

    cudaFuncSetAttribute(poly_mma_kernel,
                         cudaFuncAttributeMaxDynamicSharedMemorySize, SMEM_BYTES);
    poly_mma_kernel<<<NPAIR, THREADS, SMEM_BYTES>>>(x, mask, b1, lng, lnb, W2, b2, out);
}

// round 8
// speedup vs baseline: 1.0002x; 1.0002x over previous
#include <cuda_runtime.h>
#include <cstdint>

#define NPAIR 1024
#define THREADS 256

// ---- float-index smem offsets (compact: ~71 KB) ----
#define SA    0        // A fragments: [mt(8)][kt(16)][lane(32)][4]
#define B1S   16384
#define GS    16512
#define BTS   16640
#define SAW   16768    // [2][128]
#define PART  17024    // [mg(4)][col(128)]
#define SUMS  17536    // float2 [ng(2)][row(128)]
#define MASKI 18048    // 128 ints
#define PVI   18176    // 2 ints
#define SMEM_BYTES (18184 * 4)

__device__ __align__(256) float gBW1[3 * 16384];
__device__ __align__(256) float gBW2[3 * 16384];

__device__ __forceinline__ uint32_t to_tf32(float x) {
    uint32_t r; asm("cvt.rna.tf32.f32 %0, %1;" : "=r"(r) : "f"(x)); return r;
}
__device__ __forceinline__ float to_tf32f(float x) { return __uint_as_float(to_tf32(x)); }

__device__ __forceinline__ void mma8(float* c, uint32_t a0, uint32_t a1, uint32_t a2, uint32_t a3,
                                     uint32_t b0, uint32_t b1) {
    asm("mma.sync.aligned.m16n8k8.row.col.f32.tf32.tf32.f32 "
        "{%0,%1,%2,%3}, {%4,%5,%6,%7}, {%8,%9}, {%0,%1,%2,%3};"
        : "+f"(c[0]), "+f"(c[1]), "+f"(c[2]), "+f"(c[3])
        : "r"(a0), "r"(a1), "r"(a2), "r"(a3), "r"(b0), "r"(b1));
}

// ---------- prep: fragment-layout tf32 weight images ----------
__global__ void prep_kernel(const float* __restrict__ W1, const float* __restrict__ W2) {
    int b = blockIdx.x;            // 0..5
    int layer = b >> 1, isW2 = b & 1;
    const float* src = isW2 ? (W2 + layer * 256 * 128) : (W1 + layer * 128 * 128);
    float* dst = isW2 ? (gBW2 + layer * 16384) : (gBW1 + layer * 16384);
    for (int idx = threadIdx.x; idx < 16384; idx += blockDim.x) {
        int j = idx & 1, lane = (idx >> 1) & 31, kt = (idx >> 6) & 15, nt = idx >> 10;
        int g = lane >> 2, t = lane & 3;
        dst[idx] = to_tf32f(src[(kt * 8 + t + j * 4) * 128 + nt * 8 + g]);
    }
}

extern __shared__ float smem[];

// warp (mg,ng): rows mg*32..+31, cols ng*64..+63. B fragments streamed from L2 via LDG.
__device__ __forceinline__ void gemm64(const float* sm, const float* gB, int lid, int mg, int ng,
                                       float acc[2][8][4]) {
    #pragma unroll
    for (int m = 0; m < 2; m++)
        #pragma unroll
        for (int nt = 0; nt < 8; nt++)
            #pragma unroll
            for (int j = 0; j < 4; j++) acc[m][nt][j] = 0.0f;
    const int mt0 = mg * 2, mt1 = mt0 + 1;
    const float* base = gB + ng * 8192 + lid * 2;
    uint2 Bk[8];
    #pragma unroll
    for (int ntl = 0; ntl < 8; ntl++) Bk[ntl] = __ldg((const uint2*)(base + ntl * 1024));
    #pragma unroll 1
    for (int kt = 0; kt < 16; kt++) {
        const int ktn = (kt + 1 < 16) ? kt + 1 : 15;
        uint2 Bn[8];
        #pragma unroll
        for (int ntl = 0; ntl < 8; ntl++)
            Bn[ntl] = __ldg((const uint2*)(base + ntl * 1024 + ktn * 64));
        uint4 A0 = *(const uint4*)(sm + SA + ((mt0 * 16 + kt) * 32 + lid) * 4);
        uint4 A1 = *(const uint4*)(sm + SA + ((mt1 * 16 + kt) * 32 + lid) * 4);
        #pragma unroll
        for (int ntl = 0; ntl < 8; ntl++) {
            mma8(acc[0][ntl], A0.x, A0.z, A0.y, A0.w, Bk[ntl].x, Bk[ntl].y);
            mma8(acc[1][ntl], A1.x, A1.z, A1.y, A1.w, Bk[ntl].x, Bk[ntl].y);
        }
        #pragma unroll
        for (int ntl = 0; ntl < 8; ntl++) Bk[ntl] = Bn[ntl];
    }
}

__global__ __launch_bounds__(THREADS, 2)
void poly_mma_kernel(const float* __restrict__ x, const int* __restrict__ mask,
                     const float* __restrict__ b1,
                     const float* __restrict__ lng, const float* __restrict__ lnb,
                     const float* __restrict__ W2, const float* __restrict__ b2,
                     float* __restrict__ out)
{
    const int tid = threadIdx.x;
    const int lid = tid & 31;
    const int warp = tid >> 5;
    const int mg = warp >> 1, ng = warp & 1;
    const int gq = lid >> 2, tq = lid & 3;
    const int bid = blockIdx.x;
    // conflict-free SA writer role: this thread writes lane_t = Lw, o = o_w
    const int o_w = tq >> 1;
    const int Lw  = (tq >> 1) | ((tq & 1) << 1);
    const bool ownFirst = (tq < 2);
    int* sMask = (int*)(smem + MASKI);
    int* sPv   = (int*)(smem + PVI);

    if (tid < 128) sMask[tid] = mask[bid * 128 + tid];
    __syncthreads();
    if (tid < 2) {
        int pv = 0;
        #pragma unroll 8
        for (int p = 0; p < 64; p++) pv |= sMask[tid * 64 + p];
        sPv[tid] = pv;
    }
    __syncthreads();

    // ---- load x: thread = (row, col-half) -> A fragments (tf32) ----
    {
        const int row = tid >> 1, half = tid & 1;
        float hx[64];
        const float4* xr = (const float4*)(x + ((size_t)bid * 128 + row) * 128 + half * 64);
        const int pvMine = sPv[row >> 6];
        #pragma unroll
        for (int k = 0; k < 16; k++) {
            float4 v = xr[k];
            if (!pvMine) { v.x = 0; v.y = 0; v.z = 0; v.w = 0; }
            hx[4*k] = v.x; hx[4*k+1] = v.y; hx[4*k+2] = v.z; hx[4*k+3] = v.w;
        }
        const int mt = row >> 4, g = row & 15, gl = g & 7, jb = (g >> 3) * 2;
        #pragma unroll
        for (int ktl = 0; ktl < 8; ktl++) {
            int kt = half * 8 + ktl;
            #pragma unroll
            for (int t = 0; t < 4; t++) {
                int base = SA + ((mt * 16 + kt) * 32 + gl * 4 + t) * 4 + jb;
                smem[base]     = to_tf32f(hx[ktl * 8 + t]);
                smem[base + 1] = to_tf32f(hx[ktl * 8 + t + 4]);
            }
        }
    }

    float acc[2][8][4];

    for (int layer = 0; layer < 3; layer++) {
        if (tid < 128) {
            smem[B1S + tid] = b1[layer * 128 + tid];
            smem[GS  + tid] = lng[layer * 128 + tid];
            smem[BTS + tid] = lnb[layer * 128 + tid];
        }
        __syncthreads();                                  // S1: SA + vectors ready

        // ===== GEMM1: h @ W1 (B from L2) =====
        gemm64(smem, gBW1 + layer * 16384, lid, mg, ng, acc);

        // ===== epilogue 1: +b1, LN, ReLU; SA write (STS.128); partial col-max =====
        {
            const int pvMine = sPv[mg >> 1];
            bool vld[2][2];
            #pragma unroll
            for (int mt = 0; mt < 2; mt++)
                #pragma unroll
                for (int sb = 0; sb < 2; sb++) {
                    int r = mg * 32 + mt * 16 + gq + sb * 8;
                    vld[mt][sb] = pvMine ? (sMask[r] != 0) : true;
                }
            float s[2][2] = {{0,0},{0,0}}, q[2][2] = {{0,0},{0,0}};
            #pragma unroll
            for (int mt = 0; mt < 2; mt++)
                #pragma unroll
                for (int ntl = 0; ntl < 8; ntl++) {
                    int c0 = ng * 64 + ntl * 8 + 2 * tq;
                    float b0v = smem[B1S + c0], b1v = smem[B1S + c0 + 1];
                    float* a = acc[mt][ntl];
                    a[0] += b0v; a[1] += b1v; a[2] += b0v; a[3] += b1v;
                    s[mt][0] += a[0] + a[1]; q[mt][0] += a[0]*a[0] + a[1]*a[1];
                    s[mt][1] += a[2] + a[3]; q[mt][1] += a[2]*a[2] + a[3]*a[3];
                }
            #pragma unroll
            for (int mt = 0; mt < 2; mt++)
                #pragma unroll
                for (int sb = 0; sb < 2; sb++) {
                    s[mt][sb] += __shfl_xor_sync(0xffffffffu, s[mt][sb], 1);
                    s[mt][sb] += __shfl_xor_sync(0xffffffffu, s[mt][sb], 2);
                    q[mt][sb] += __shfl_xor_sync(0xffffffffu, q[mt][sb], 1);
                    q[mt][sb] += __shfl_xor_sync(0xffffffffu, q[mt][sb], 2);
                }
            if (tq == 0) {
                float2* su = (float2*)(smem + SUMS);
                #pragma unroll
                for (int mt = 0; mt < 2; mt++)
                    #pragma unroll
                    for (int sb = 0; sb < 2; sb++) {
                        int r = mg * 32 + mt * 16 + gq + sb * 8;
                        su[ng * 128 + r] = make_float2(s[mt][sb], q[mt][sb]);
                    }
            }
            __syncthreads();                               // S2: sums ready; GEMM1 reads done
            float mean[2][2], rstd[2][2];
            {
                const float2* su = (const float2*)(smem + SUMS);
                #pragma unroll
                for (int mt = 0; mt < 2; mt++)
                    #pragma unroll
                    for (int sb = 0; sb < 2; sb++) {
                        int r = mg * 32 + mt * 16 + gq + sb * 8;
                        float2 u = su[r], v = su[128 + r];
                        float m = (u.x + v.x) * (1.0f / 128.0f);
                        float var = (u.y + v.y) * (1.0f / 128.0f) - m * m;
                        mean[mt][sb] = m;
                        rstd[mt][sb] = rsqrtf(var + 1e-5f);
                    }
            }
            float pm[8][2];
            #pragma unroll
            for (int ntl = 0; ntl < 8; ntl++) { pm[ntl][0] = -INFINITY; pm[ntl][1] = -INFINITY; }
            #pragma unroll
            for (int mt = 0; mt < 2; mt++)
                #pragma unroll
                for (int ntl = 0; ntl < 8; ntl++) {
                    int nt = ng * 8 + ntl;
                    int c0 = nt * 8 + 2 * tq;
                    float g0 = smem[GS + c0], g1 = smem[GS + c0 + 1];
                    float t0 = smem[BTS + c0], t1 = smem[BTS + c0 + 1];
                    float v2[2][2];  // [sb][o]
                    #pragma unroll
                    for (int idx = 0; idx < 4; idx++) {
                        int sb = idx >> 1, o = idx & 1;
                        float hv = fmaxf(fmaf((acc[mt][ntl][idx] - mean[mt][sb]) * rstd[mt][sb],
                                              o ? g1 : g0, o ? t1 : t0), 0.0f);
                        v2[sb][o] = to_tf32f(hv);
                        pm[ntl][o] = fmaxf(pm[ntl][o], vld[mt][sb] ? hv : -INFINITY);
                    }
                    // quad exchange -> one STS.128
                    float own0 = v2[0][o_w], own1 = v2[1][o_w];
                    float rcv0 = __shfl_xor_sync(0xffffffffu, v2[0][1 - o_w], 2);
                    float rcv1 = __shfl_xor_sync(0xffffffffu, v2[1][1 - o_w], 2);
                    float4 w = ownFirst ? make_float4(own0, rcv0, own1, rcv1)
                                        : make_float4(rcv0, own0, rcv1, own1);
                    *(float4*)(smem + SA + (((mg * 2 + mt) * 16 + nt) * 32 + gq * 4 + Lw) * 4) = w;
                }
            #pragma unroll
            for (int ntl = 0; ntl < 8; ntl++) {
                #pragma unroll
                for (int off = 4; off <= 16; off <<= 1) {
                    pm[ntl][0] = fmaxf(pm[ntl][0], __shfl_xor_sync(0xffffffffu, pm[ntl][0], off));
                    pm[ntl][1] = fmaxf(pm[ntl][1], __shfl_xor_sync(0xffffffffu, pm[ntl][1], off));
                }
                if (gq == 0) {
                    smem[PART + mg * 128 + ng * 64 + ntl * 8 + 2 * tq]     = pm[ntl][0];
                    smem[PART + mg * 128 + ng * 64 + ntl * 8 + 2 * tq + 1] = pm[ntl][1];
                }
            }
        }
        __syncthreads();                                    // S3: PART + SA(h2) ready

        // ---- aggW = b2 + (max over points) @ W2b, 256 threads ----
        {
            int poly = tid >> 7, col = tid & 127;
            float sacc = b2[layer * 128 + col];
            const float* w2b = W2 + layer * 256 * 128 + 128 * 128 + col;
            const float* p0 = smem + PART + poly * 256;
            #pragma unroll 8
            for (int d = 0; d < 128; d++) {
                float a = fmaxf(p0[d], p0[128 + d]);
                sacc = fmaf(a, __ldg(w2b + d * 128), sacc);
            }
            smem[SAW + poly * 128 + col] = sacc;
        }
        __syncthreads();                                    // S4: SAW ready

        // ===== GEMM2: h2 @ W2a (B from L2) =====
        gemm64(smem, gBW2 + layer * 16384, lid, mg, ng, acc);
        __syncthreads();                                    // S4b: all GEMM2 SA reads done

        // ===== epilogue 2: + aggW ; SA write (STS.128) or final partial max =====
        {
            const float* saw = smem + SAW + (mg >> 1) * 128;
            if (layer < 2) {
                #pragma unroll
                for (int mt = 0; mt < 2; mt++)
                    #pragma unroll
                    for (int ntl = 0; ntl < 8; ntl++) {
                        int nt = ng * 8 + ntl;
                        int c0 = nt * 8 + 2 * tq;
                        float w0 = saw[c0], w1 = saw[c0 + 1];
                        float v2[2][2];
                        #pragma unroll
                        for (int idx = 0; idx < 4; idx++) {
                            int sb = idx >> 1, o = idx & 1;
                            v2[sb][o] = to_tf32f(acc[mt][ntl][idx] + (o ? w1 : w0));
                        }
                        float own0 = v2[0][o_w], own1 = v2[1][o_w];
                        float rcv0 = __shfl_xor_sync(0xffffffffu, v2[0][1 - o_w], 2);
                        float rcv1 = __shfl_xor_sync(0xffffffffu, v2[1][1 - o_w], 2);
                        float4 w = ownFirst ? make_float4(own0, rcv0, own1, rcv1)
                                            : make_float4(rcv0, own0, rcv1, own1);
                        *(float4*)(smem + SA + (((mg * 2 + mt) * 16 + nt) * 32 + gq * 4 + Lw) * 4) = w;
                    }
            } else {
                const int pvMine = sPv[mg >> 1];
                bool vld[2][2];
                #pragma unroll
                for (int mt = 0; mt < 2; mt++)
                    #pragma unroll
                    for (int sb = 0; sb < 2; sb++) {
                        int r = mg * 32 + mt * 16 + gq + sb * 8;
                        vld[mt][sb] = pvMine ? (sMask[r] != 0) : true;
                    }
                float pm[8][2];
                #pragma unroll
                for (int ntl = 0; ntl < 8; ntl++) { pm[ntl][0] = -INFINITY; pm[ntl][1] = -INFINITY; }
                #pragma unroll
                for (int mt = 0; mt < 2; mt++)
                    #pragma unroll
                    for (int ntl = 0; ntl < 8; ntl++) {
                        int c0 = ng * 64 + ntl * 8 + 2 * tq;
                        float w0 = saw[c0], w1 = saw[c0 + 1];
                        #pragma unroll
                        for (int idx = 0; idx < 4; idx++) {
                            int sb = idx >> 1, o = idx & 1;
                            float v = acc[mt][ntl][idx] + (o ? w1 : w0);
                            pm[ntl][o] = fmaxf(pm[ntl][o], vld[mt][sb] ? v : -INFINITY);
                        }
                    }
                #pragma unroll
                for (int ntl = 0; ntl < 8; ntl++) {
                    #pragma unroll
                    for (int off = 4; off <= 16; off <<= 1) {
                        pm[ntl][0] = fmaxf(pm[ntl][0], __shfl_xor_sync(0xffffffffu, pm[ntl][0], off));
                        pm[ntl][1] = fmaxf(pm[ntl][1], __shfl_xor_sync(0xffffffffu, pm[ntl][1], off));
                    }
                    if (gq == 0) {
                        smem[PART + mg * 128 + ng * 64 + ntl * 8 + 2 * tq]     = pm[ntl][0];
                        smem[PART + mg * 128 + ng * 64 + ntl * 8 + 2 * tq + 1] = pm[ntl][1];
                    }
                }
            }
        }
        __syncthreads();                                    // S5: SA/PART ready for next phase
    }

    {
        int poly = tid >> 7, col = tid & 127;
        float m = fmaxf(smem[PART + poly * 256 + col], smem[PART + poly * 256 + 128 + col]);
        out[(size_t)(bid * 2 + poly) * 128 + col] = sPv[poly] ? m : 0.0f;
    }
}

extern "C" void kernel_launch(void* const* d_in, const int* in_sizes, int n_in,
                              void* d_out, int out_size) {
    const float* x    = (const float*)d_in[0];
    const int*   mask = (const int*)d_in[1];
    const float* W1   = (const float*)d_in[2];
    const float* b1   = (const float*)d_in[3];
    const float* lng  = (const float*)d_in[4];
    const float* lnb  = (const float*)d_in[5];
    const float* W2   = (const float*)d_in[6];
    const float* b2   = (const float*)d_in[7];
    float*       out  = (float*)d_out;

    prep_kernel<<<6, 256>>>(W1, W2);

    cudaFuncSetAttribute(poly_mma_kernel,
                         cudaFuncAttributeMaxDynamicSharedMemorySize, SMEM_BYTES);
    poly_mma_kernel<<<NPAIR, THREADS, SMEM_BYTES>>>(x, mask, b1, lng, lnb, W2, b2, out);
}